// round 15
// baseline (speedup 1.0000x reference)
#include <cuda_runtime.h>
#include <cuda_bf16.h>

// Problem constants
#define TT    8192
#define NN    10
#define FIN   7
#define NF    70      // N*F_IN
#define NFP   72      // padded
#define OO    64
#define HH    512
#define G4    2048    // 4*H
#define LAT   128
#define EE    40
#define RR    2
#define NBLK  64      // recurrent blocks
#define CBLK  84      // concurrent k5-consumer blocks (64+84 = 148 SMs)
#define HC    8       // H cells per block (512/64)
#define T6    16      // timesteps per block in k6

// Scratch (device globals; no dynamic allocation allowed)
__device__ float              g_G[NN * NN * FIN * OO];   // [n][m][f][o]
__device__ float              g_M[G4 * NFP];             // [2048][72]
__device__ float              g_biasx[G4];
__device__ float              g_Xp[(size_t)TT * G4];     // [t][cell*4+gate]
// (tag<<32)|h_bits, double-buffered; ONE pair (2 cells) per 128B line.
__device__ unsigned long long g_hpk[2][HH / 2][16];
__device__ float4             g_hs4[TT * HH / 4];        // all h_t (16.8 MB)

#define REC_OFF 0
#define MU_OFF  (TT * NN * FIN)                 // 573440
#define LV_OFF  (MU_OFF + TT * LAT)             // 1622016

// ---------------------------------------------------------------------------
// K1: build G[n][m][f][o] from edges
// ---------------------------------------------------------------------------
__global__ void k1_build_G(const float* __restrict__ Wrel,
                           const float* __restrict__ Wroot,
                           const int*   __restrict__ eidx,
                           const int*   __restrict__ etyp) {
    __shared__ int   cc[RR][NN][NN];
    __shared__ float inv[RR][NN];
    int tid = threadIdx.x;
    for (int i = tid; i < RR * NN * NN; i += 256) ((int*)cc)[i] = 0;
    __syncthreads();
    if (tid < EE) {
        int s = eidx[tid];
        int d = eidx[EE + tid];
        int r = etyp[tid];
        atomicAdd(&cc[r][d][s], 1);
    }
    __syncthreads();
    if (tid < RR * NN) {
        int r = tid / NN, n = tid % NN;
        int cnt = 0;
        for (int m = 0; m < NN; m++) cnt += cc[r][n][m];
        inv[r][n] = 1.0f / fmaxf((float)cnt, 1.0f);
    }
    __syncthreads();
    for (int idx = tid; idx < NN * NN * FIN * OO; idx += 256) {
        int o = idx & 63;
        int f = (idx >> 6) % FIN;
        int m = (idx / (FIN * OO)) % NN;
        int n = idx / (NN * FIN * OO);
        float v = inv[0][n] * (float)cc[0][n][m] * Wrel[(0 * FIN + f) * OO + o]
                + inv[1][n] * (float)cc[1][n][m] * Wrel[(1 * FIN + f) * OO + o];
        if (n == m) v += Wroot[f * OO + o];
        g_G[idx] = v;
    }
}

// ---------------------------------------------------------------------------
// K2: M = W_ih * A  (2048x72), biasx = b_ih + b_hh + W_ih*b_rgcn
// ---------------------------------------------------------------------------
__global__ void k2_build_M(const float* __restrict__ Wih,
                           const float* __restrict__ bih,
                           const float* __restrict__ bhh,
                           const float* __restrict__ brg) {
    __shared__ float Aw[64][65];
    __shared__ float Bg[80][65];
    int g0  = blockIdx.x * 64;
    int tid = threadIdx.x;
    int ty  = tid >> 4, tx = tid & 15;
    float acc[4][5];
#pragma unroll
    for (int u = 0; u < 4; u++)
#pragma unroll
        for (int v = 0; v < 5; v++) acc[u][v] = 0.0f;

    for (int n = 0; n < NN; n++) {
        __syncthreads();
        for (int i = tid; i < 64 * 64; i += 256) {
            int r = i >> 6, c = i & 63;
            Aw[r][c] = Wih[(g0 + r) * (NN * OO) + n * OO + c];
        }
        for (int i = tid; i < 80 * 64; i += 256) {
            int j = i >> 6, o = i & 63;
            Bg[j][o] = (j < NF)
                ? g_G[((n * NN + (j / FIN)) * FIN + (j % FIN)) * OO + o]
                : 0.0f;
        }
        __syncthreads();
        for (int o = 0; o < 64; o++) {
            float a[4], b[5];
#pragma unroll
            for (int u = 0; u < 4; u++) a[u] = Aw[ty * 4 + u][o];
#pragma unroll
            for (int v = 0; v < 5; v++) b[v] = Bg[tx * 5 + v][o];
#pragma unroll
            for (int u = 0; u < 4; u++)
#pragma unroll
                for (int v = 0; v < 5; v++) acc[u][v] += a[u] * b[v];
        }
    }
#pragma unroll
    for (int u = 0; u < 4; u++)
#pragma unroll
        for (int v = 0; v < 5; v++) {
            int j = tx * 5 + v;
            if (j < NFP)
                g_M[(g0 + ty * 4 + u) * NFP + j] = acc[u][v];
        }

    __syncthreads();
    if (tid < 64) {
        int g = g0 + tid;
        float s = bih[g] + bhh[g];
        for (int q = 0; q < NN * OO; q++) s += Wih[g * (NN * OO) + q] * brg[q & 63];
        g_biasx[g] = s;
    }
}

// ---------------------------------------------------------------------------
// K3: reset tagged h words (must run before K4 on every graph replay)
// ---------------------------------------------------------------------------
__global__ void k3_reset() {
    int tid = threadIdx.x;
    for (int i = tid; i < 2 * (HH / 2) * 16; i += 256)
        ((unsigned long long*)g_hpk)[i] = 0ull;   // tag 0, value 0.0f
}

// ---------------------------------------------------------------------------
// K6 (R14, measured 79us): register-tiled GEMM Xp = biasx + M.x
// ---------------------------------------------------------------------------
__global__ void __launch_bounds__(256)
k6_xpre(const float* __restrict__ x) {
    __shared__ float shx_t[NFP][T6];   // [72][16] transposed
    int tid  = threadIdx.x;
    int tc   = blockIdx.x >> 1;
    int half = blockIdx.x & 1;
    int t0   = tc * T6;

    for (int i = tid; i < T6 * NF; i += 256) {
        int tt = i / NF, j = i % NF;
        shx_t[j][tt] = x[(size_t)(t0 + tt) * NF + j];
    }
    if (tid < 2 * T6) shx_t[70 + (tid >> 4)][tid & 15] = 0.0f;
    __syncthreads();

    const int idx0 = half * 1024 + tid * 4;
    const int cell = idx0 >> 2;

    float bias[4];
#pragma unroll
    for (int g = 0; g < 4; g++) bias[g] = g_biasx[g * HH + cell];

    float acc[4][T6];
#pragma unroll
    for (int g = 0; g < 4; g++)
#pragma unroll
        for (int t = 0; t < T6; t++) acc[g][t] = 0.0f;

#pragma unroll
    for (int jc = 0; jc < NFP / 8; jc++) {
        float ms[4][8];
#pragma unroll
        for (int g = 0; g < 4; g++) {
            const float4* mp =
                (const float4*)&g_M[(g * HH + cell) * NFP + jc * 8];
            float4 a = mp[0], b = mp[1];
            ms[g][0] = a.x; ms[g][1] = a.y; ms[g][2] = a.z; ms[g][3] = a.w;
            ms[g][4] = b.x; ms[g][5] = b.y; ms[g][6] = b.z; ms[g][7] = b.w;
        }
#pragma unroll
        for (int jj = 0; jj < 8; jj++) {
            int j = jc * 8 + jj;
#pragma unroll
            for (int tg = 0; tg < 4; tg++) {
                float4 xv = *(const float4*)&shx_t[j][tg * 4];
#pragma unroll
                for (int g = 0; g < 4; g++) {
                    acc[g][tg * 4 + 0] += ms[g][jj] * xv.x;
                    acc[g][tg * 4 + 1] += ms[g][jj] * xv.y;
                    acc[g][tg * 4 + 2] += ms[g][jj] * xv.z;
                    acc[g][tg * 4 + 3] += ms[g][jj] * xv.w;
                }
            }
        }
    }

#pragma unroll
    for (int t = 0; t < T6; t++) {
        float4 o;
        o.x = bias[0] + acc[0][t];
        o.y = bias[1] + acc[1][t];
        o.z = bias[2] + acc[2][t];
        o.w = bias[3] + acc[3][t];
        *(float4*)&g_Xp[(size_t)(t0 + t) * G4 + idx0] = o;
    }
}

// ---------------------------------------------------------------------------
// K4K5 fused: blocks 0..63 = LSTM (R9 protocol, unchanged except tag store
// is st.release to cover the ghs history writes); blocks 64..147 = k5
// consumers that tile-process fc1/VAE/fc2 concurrently, gated on h tags.
// ---------------------------------------------------------------------------
struct K4Sh { float sh_h[2][8 * 68]; };
struct K5Sh { float shh[8 * HH]; float shfc[8][256]; float shz[8][LAT]; };

__global__ void __launch_bounds__(256, 1)
k4k5(const float* __restrict__ Whh,
     const float* __restrict__ eps,
     const float* __restrict__ fc1w, const float* __restrict__ fc1b,
     const float* __restrict__ fc2w, const float* __restrict__ fc2b,
     float* __restrict__ out) {
    __shared__ union { K4Sh a; K5Sh b; } sh;
    const int tid = threadIdx.x;

    if (blockIdx.x < NBLK) {
        // =================== LSTM path (byte-equivalent to R9/R14) ==========
        float (*sh_h)[8 * 68] = sh.a.sh_h;
        const int w    = tid >> 5;
        const int l    = tid & 31;
        const int bid  = blockIdx.x;
        const int gate = l & 3;
        const int cc   = l >> 2;
        const int cell = bid * HC + w;
        const int xidx = (cell << 2) + gate;
        (void)w;

        unsigned long long wp01[16], wp23[16];
        {
            const ulonglong2* wp =
                (const ulonglong2*)(Whh + (size_t)(gate * HH + cell) * HH + cc * 64);
#pragma unroll
            for (int i = 0; i < 16; i++) { ulonglong2 v = wp[i]; wp01[i] = v.x; wp23[i] = v.y; }
        }

        const int pc   = 2 * tid;
        const int spos = (pc >> 6) * 68 + (pc & 63);

        for (int i = tid; i < 8 * 68; i += 256) sh_h[0][i] = 0.0f;
        float xp0 = __ldcg(&g_Xp[(size_t)0 * G4 + xidx]);
        float xp1 = __ldcg(&g_Xp[(size_t)1 * G4 + xidx]);
        __syncthreads();

        float c = 0.0f;
        float* ghs = (float*)g_hs4;
        unsigned long long v0 = 0ull, v1 = 0ull;

        for (int t = 0; t < TT; t++) {
            if (t > 0) {
                const unsigned long long* pp = &g_hpk[(t + 1) & 1][tid][0];
                unsigned long long u0, u1;
                asm volatile("ld.relaxed.gpu.global.v2.u64 {%0,%1}, [%2];"
                             : "=l"(u0), "=l"(u1) : "l"(pp) : "memory");
                const unsigned tt = (unsigned)t;
                if ((unsigned)(v0 >> 32) < tt || (unsigned)(v1 >> 32) < tt) {
                    v0 = u0; v1 = u1;
                    while ((unsigned)(v0 >> 32) < tt || (unsigned)(v1 >> 32) < tt) {
                        asm volatile("ld.relaxed.gpu.global.v2.u64 {%0,%1}, [%2];"
                                     : "=l"(v0), "=l"(v1) : "l"(pp) : "memory");
                    }
                }
                *(float2*)&sh_h[t & 1][spos] =
                    make_float2(__uint_as_float((unsigned)v0),
                                __uint_as_float((unsigned)v1));
            }
            __syncthreads();

            unsigned long long a01 = 0ull, a23 = 0ull;
            {
                const ulonglong2* hb = (const ulonglong2*)&sh_h[t & 1][cc * 68];
#pragma unroll
                for (int i = 0; i < 16; i++) {
                    ulonglong2 hv = hb[i];
                    asm("fma.rn.f32x2 %0, %1, %2, %0;"
                        : "+l"(a01) : "l"(wp01[i]), "l"(hv.x));
                    asm("fma.rn.f32x2 %0, %1, %2, %0;"
                        : "+l"(a23) : "l"(wp23[i]), "l"(hv.y));
                }
            }
            float s;
            {
                unsigned lo0, hi0, lo1, hi1;
                asm("mov.b64 {%0,%1}, %2;" : "=r"(lo0), "=r"(hi0) : "l"(a01));
                asm("mov.b64 {%0,%1}, %2;" : "=r"(lo1), "=r"(hi1) : "l"(a23));
                s = (__uint_as_float(lo0) + __uint_as_float(hi0))
                  + (__uint_as_float(lo1) + __uint_as_float(hi1));
            }
            s += __shfl_xor_sync(0xffffffffu, s, 4);
            s += __shfl_xor_sync(0xffffffffu, s, 8);
            s += __shfl_xor_sync(0xffffffffu, s, 16);
            s += xp0;

            const bool tg = (gate == 2);
            float arg = tg ? 2.0f * s : s;
            float sg  = __fdividef(1.0f, 1.0f + __expf(-arg));
            float act = tg ? 2.0f * sg - 1.0f : sg;

            float iv = __shfl_sync(0xffffffffu, act, 0, 4);
            float fv = __shfl_sync(0xffffffffu, act, 1, 4);
            float gv = __shfl_sync(0xffffffffu, act, 2, 4);
            float ov = __shfl_sync(0xffffffffu, act, 3, 4);

            c = fv * c + iv * gv;
            float th = 2.0f * __fdividef(1.0f, 1.0f + __expf(-2.0f * c)) - 1.0f;
            float hv = ov * th;

            if (l == 0) {
                ghs[(size_t)t * HH + cell] = hv;   // history (covered by release)
                unsigned long long pk =
                    ((unsigned long long)(unsigned)(t + 1) << 32) |
                    (unsigned long long)__float_as_uint(hv);
                asm volatile("st.release.gpu.global.u64 [%0], %1;"
                             :: "l"(&g_hpk[t & 1][cell >> 1][cell & 1]), "l"(pk)
                             : "memory");
            }

            xp0 = xp1;
            xp1 = (t + 2 < TT) ? __ldcg(&g_Xp[(size_t)(t + 2) * G4 + xidx]) : 0.0f;

            {
                const unsigned long long* pn = &g_hpk[t & 1][tid][0];
                asm volatile("ld.relaxed.gpu.global.v2.u64 {%0,%1}, [%2];"
                             : "=l"(v0), "=l"(v1) : "l"(pn) : "memory");
            }
        }
    } else {
        // =================== k5 consumer path ===============================
        float* shh = sh.b.shh;
        float (*shfc)[256] = sh.b.shfc;
        float (*shz)[LAT]  = sh.b.shz;
        const int w    = tid >> 5;
        const int lane = tid & 31;
        const int cidx = blockIdx.x - NBLK;

        for (int tile = cidx; tile < TT / 8; tile += CBLK) {
            const int t0 = tile * 8;
            const unsigned target =
                (unsigned)((t0 + 8 < TT) ? (t0 + 8) : TT);

            // wait until both cells of line tid have (max-over-buffer) tag >= target
            {
                float bo = 1.0f;
                for (;;) {
                    unsigned long long a0, a1, b0, b1;
                    asm volatile("ld.acquire.gpu.global.v2.u64 {%0,%1}, [%2];"
                                 : "=l"(a0), "=l"(a1)
                                 : "l"(&g_hpk[0][tid][0]) : "memory");
                    asm volatile("ld.acquire.gpu.global.v2.u64 {%0,%1}, [%2];"
                                 : "=l"(b0), "=l"(b1)
                                 : "l"(&g_hpk[1][tid][0]) : "memory");
                    unsigned m0 = (unsigned)(a0 >> 32), m1 = (unsigned)(a1 >> 32);
                    unsigned n0 = (unsigned)(b0 >> 32), n1 = (unsigned)(b1 >> 32);
                    unsigned c0 = m0 > n0 ? m0 : n0;
                    unsigned c1 = m1 > n1 ? m1 : n1;
                    if (c0 >= target && c1 >= target) break;
                    // ~2000-cycle dependent backoff to keep poll traffic tiny
#pragma unroll 1
                    for (int i = 0; i < 256; i++)
                        asm volatile("add.f32 %0,%0,0f3F800000;" : "+f"(bo));
                }
            }
            __syncthreads();

            for (int i = tid; i < 8 * HH / 4; i += 256)
                ((float4*)shh)[i] =
                    ((const float4*)g_hs4)[(size_t)t0 * (HH / 4) + i];
            __syncthreads();

            // fc1
            for (int i = 0; i < 32; i++) {
                int j = w * 32 + i;
                float wr[16];
#pragma unroll
                for (int u = 0; u < 16; u++)
                    wr[u] = __ldg(fc1w + (size_t)j * HH + u * 32 + lane);
#pragma unroll
                for (int ttk = 0; ttk < 8; ttk++) {
                    float p = 0.0f;
#pragma unroll
                    for (int u = 0; u < 16; u++)
                        p += wr[u] * shh[ttk * HH + u * 32 + lane];
                    p += __shfl_xor_sync(0xffffffffu, p, 16);
                    p += __shfl_xor_sync(0xffffffffu, p, 8);
                    p += __shfl_xor_sync(0xffffffffu, p, 4);
                    p += __shfl_xor_sync(0xffffffffu, p, 2);
                    p += __shfl_xor_sync(0xffffffffu, p, 1);
                    if (lane == 0) shfc[ttk][j] = fmaxf(p + fc1b[j], 0.0f);
                }
            }
            __syncthreads();

            // VAE reparam + mu / log_var
            for (int i = tid; i < 8 * LAT; i += 256) {
                int ttk = i >> 7, j = i & 127;
                int t = t0 + ttk;
                float mu = shfc[ttk][j];
                float lv = shfc[ttk][LAT + j];
                out[MU_OFF + (size_t)t * LAT + j] = mu;
                out[LV_OFF + (size_t)t * LAT + j] = lv;
                shz[ttk][j] = mu + eps[(size_t)t * LAT + j] * expf(0.5f * lv);
            }
            __syncthreads();

            // fc2 + sigmoid -> rec
            for (int i = 0; i < 9; i++) {
                int j = w + 8 * i;
                if (j < NF) {
                    float wr[4];
#pragma unroll
                    for (int u = 0; u < 4; u++)
                        wr[u] = __ldg(fc2w + (size_t)j * LAT + u * 32 + lane);
#pragma unroll
                    for (int ttk = 0; ttk < 8; ttk++) {
                        float p = 0.0f;
#pragma unroll
                        for (int u = 0; u < 4; u++)
                            p += wr[u] * shz[ttk][u * 32 + lane];
                        p += __shfl_xor_sync(0xffffffffu, p, 16);
                        p += __shfl_xor_sync(0xffffffffu, p, 8);
                        p += __shfl_xor_sync(0xffffffffu, p, 4);
                        p += __shfl_xor_sync(0xffffffffu, p, 2);
                        p += __shfl_xor_sync(0xffffffffu, p, 1);
                        if (lane == 0)
                            out[REC_OFF + (size_t)(t0 + ttk) * NF + j] =
                                1.0f / (1.0f + expf(-(p + fc2b[j])));
                    }
                }
            }
            __syncthreads();   // before next tile reuses shared
        }
    }
}

// ---------------------------------------------------------------------------
extern "C" void kernel_launch(void* const* d_in, const int* in_sizes, int n_in,
                              void* d_out, int out_size) {
    const float* x     = (const float*)d_in[0];
    const float* eps   = (const float*)d_in[1];
    const float* Wrel  = (const float*)d_in[2];
    const float* Wroot = (const float*)d_in[3];
    const float* brg   = (const float*)d_in[4];
    const float* Wih   = (const float*)d_in[5];
    const float* Whh   = (const float*)d_in[6];
    const float* bih   = (const float*)d_in[7];
    const float* bhh   = (const float*)d_in[8];
    const float* fc1w  = (const float*)d_in[9];
    const float* fc1b  = (const float*)d_in[10];
    const float* fc2w  = (const float*)d_in[11];
    const float* fc2b  = (const float*)d_in[12];
    const int*   eidx  = (const int*)d_in[13];
    const int*   etyp  = (const int*)d_in[14];
    float* out = (float*)d_out;

    k1_build_G<<<1, 256>>>(Wrel, Wroot, eidx, etyp);
    k2_build_M<<<32, 256>>>(Wih, bih, bhh, brg);
    k3_reset<<<1, 256>>>();
    k6_xpre<<<2 * (TT / T6), 256>>>(x);
    k4k5<<<NBLK + CBLK, 256>>>(Whh, eps, fc1w, fc1b, fc2w, fc2b, out);
}

// round 16
// speedup vs baseline: 1.3514x; 1.3514x over previous
#include <cuda_runtime.h>
#include <cuda_bf16.h>

// Problem constants
#define TT    8192
#define NN    10
#define FIN   7
#define NF    70      // N*F_IN
#define NFP   72      // padded
#define OO    64
#define HH    512
#define G4    2048    // 4*H
#define LAT   128
#define EE    40
#define RR    2
#define NBLK  64      // recurrent blocks
#define HC    8       // H cells per block (512/64)
#define T6    16      // timesteps per block in k6
#define T5    16      // timesteps per block in k5

// Scratch (device globals; no dynamic allocation allowed)
__device__ float              g_G[NN * NN * FIN * OO];   // [n][m][f][o]
__device__ float              g_M[G4 * NFP];             // [2048][72]
__device__ float              g_biasx[G4];
__device__ float              g_Xp[(size_t)TT * G4];     // [t][cell*4+gate]
// (tag<<32)|h_bits, double-buffered; ONE pair (2 cells) per 128B line.
__device__ unsigned long long g_hpk[2][HH / 2][16];
__device__ float4             g_hs4[TT * HH / 4];        // all h_t (16.8 MB)

// ---------------------------------------------------------------------------
// K1: build G[n][m][f][o] from edges
// ---------------------------------------------------------------------------
__global__ void k1_build_G(const float* __restrict__ Wrel,
                           const float* __restrict__ Wroot,
                           const int*   __restrict__ eidx,
                           const int*   __restrict__ etyp) {
    __shared__ int   cc[RR][NN][NN];
    __shared__ float inv[RR][NN];
    int tid = threadIdx.x;
    for (int i = tid; i < RR * NN * NN; i += 256) ((int*)cc)[i] = 0;
    __syncthreads();
    if (tid < EE) {
        int s = eidx[tid];
        int d = eidx[EE + tid];
        int r = etyp[tid];
        atomicAdd(&cc[r][d][s], 1);
    }
    __syncthreads();
    if (tid < RR * NN) {
        int r = tid / NN, n = tid % NN;
        int cnt = 0;
        for (int m = 0; m < NN; m++) cnt += cc[r][n][m];
        inv[r][n] = 1.0f / fmaxf((float)cnt, 1.0f);
    }
    __syncthreads();
    for (int idx = tid; idx < NN * NN * FIN * OO; idx += 256) {
        int o = idx & 63;
        int f = (idx >> 6) % FIN;
        int m = (idx / (FIN * OO)) % NN;
        int n = idx / (NN * FIN * OO);
        float v = inv[0][n] * (float)cc[0][n][m] * Wrel[(0 * FIN + f) * OO + o]
                + inv[1][n] * (float)cc[1][n][m] * Wrel[(1 * FIN + f) * OO + o];
        if (n == m) v += Wroot[f * OO + o];
        g_G[idx] = v;
    }
}

// ---------------------------------------------------------------------------
// K2: M = W_ih * A  (2048x72), biasx = b_ih + b_hh + W_ih*b_rgcn
// ---------------------------------------------------------------------------
__global__ void k2_build_M(const float* __restrict__ Wih,
                           const float* __restrict__ bih,
                           const float* __restrict__ bhh,
                           const float* __restrict__ brg) {
    __shared__ float Aw[64][65];
    __shared__ float Bg[80][65];
    int g0  = blockIdx.x * 64;
    int tid = threadIdx.x;
    int ty  = tid >> 4, tx = tid & 15;
    float acc[4][5];
#pragma unroll
    for (int u = 0; u < 4; u++)
#pragma unroll
        for (int v = 0; v < 5; v++) acc[u][v] = 0.0f;

    for (int n = 0; n < NN; n++) {
        __syncthreads();
        for (int i = tid; i < 64 * 64; i += 256) {
            int r = i >> 6, c = i & 63;
            Aw[r][c] = Wih[(g0 + r) * (NN * OO) + n * OO + c];
        }
        for (int i = tid; i < 80 * 64; i += 256) {
            int j = i >> 6, o = i & 63;
            Bg[j][o] = (j < NF)
                ? g_G[((n * NN + (j / FIN)) * FIN + (j % FIN)) * OO + o]
                : 0.0f;
        }
        __syncthreads();
        for (int o = 0; o < 64; o++) {
            float a[4], b[5];
#pragma unroll
            for (int u = 0; u < 4; u++) a[u] = Aw[ty * 4 + u][o];
#pragma unroll
            for (int v = 0; v < 5; v++) b[v] = Bg[tx * 5 + v][o];
#pragma unroll
            for (int u = 0; u < 4; u++)
#pragma unroll
                for (int v = 0; v < 5; v++) acc[u][v] += a[u] * b[v];
        }
    }
#pragma unroll
    for (int u = 0; u < 4; u++)
#pragma unroll
        for (int v = 0; v < 5; v++) {
            int j = tx * 5 + v;
            if (j < NFP)
                g_M[(g0 + ty * 4 + u) * NFP + j] = acc[u][v];
        }

    __syncthreads();
    if (tid < 64) {
        int g = g0 + tid;
        float s = bih[g] + bhh[g];
        for (int q = 0; q < NN * OO; q++) s += Wih[g * (NN * OO) + q] * brg[q & 63];
        g_biasx[g] = s;
    }
}

// ---------------------------------------------------------------------------
// K3: reset tagged h words (must run before K4 on every graph replay)
// ---------------------------------------------------------------------------
__global__ void k3_reset() {
    int tid = threadIdx.x;
    for (int i = tid; i < 2 * (HH / 2) * 16; i += 256)
        ((unsigned long long*)g_hpk)[i] = 0ull;   // tag 0, value 0.0f
}

// ---------------------------------------------------------------------------
// K6 (R14, measured 79us): register-tiled GEMM Xp = biasx + M.x
// ---------------------------------------------------------------------------
__global__ void __launch_bounds__(256)
k6_xpre(const float* __restrict__ x) {
    __shared__ float shx_t[NFP][T6];   // [72][16] transposed
    int tid  = threadIdx.x;
    int tc   = blockIdx.x >> 1;
    int half = blockIdx.x & 1;
    int t0   = tc * T6;

    for (int i = tid; i < T6 * NF; i += 256) {
        int tt = i / NF, j = i % NF;
        shx_t[j][tt] = x[(size_t)(t0 + tt) * NF + j];
    }
    if (tid < 2 * T6) shx_t[70 + (tid >> 4)][tid & 15] = 0.0f;
    __syncthreads();

    const int idx0 = half * 1024 + tid * 4;
    const int cell = idx0 >> 2;

    float bias[4];
#pragma unroll
    for (int g = 0; g < 4; g++) bias[g] = g_biasx[g * HH + cell];

    float acc[4][T6];
#pragma unroll
    for (int g = 0; g < 4; g++)
#pragma unroll
        for (int t = 0; t < T6; t++) acc[g][t] = 0.0f;

#pragma unroll
    for (int jc = 0; jc < NFP / 8; jc++) {
        float ms[4][8];
#pragma unroll
        for (int g = 0; g < 4; g++) {
            const float4* mp =
                (const float4*)&g_M[(g * HH + cell) * NFP + jc * 8];
            float4 a = mp[0], b = mp[1];
            ms[g][0] = a.x; ms[g][1] = a.y; ms[g][2] = a.z; ms[g][3] = a.w;
            ms[g][4] = b.x; ms[g][5] = b.y; ms[g][6] = b.z; ms[g][7] = b.w;
        }
#pragma unroll
        for (int jj = 0; jj < 8; jj++) {
            int j = jc * 8 + jj;
#pragma unroll
            for (int tg = 0; tg < 4; tg++) {
                float4 xv = *(const float4*)&shx_t[j][tg * 4];
#pragma unroll
                for (int g = 0; g < 4; g++) {
                    acc[g][tg * 4 + 0] += ms[g][jj] * xv.x;
                    acc[g][tg * 4 + 1] += ms[g][jj] * xv.y;
                    acc[g][tg * 4 + 2] += ms[g][jj] * xv.z;
                    acc[g][tg * 4 + 3] += ms[g][jj] * xv.w;
                }
            }
        }
    }

#pragma unroll
    for (int t = 0; t < T6; t++) {
        float4 o;
        o.x = bias[0] + acc[0][t];
        o.y = bias[1] + acc[1][t];
        o.z = bias[2] + acc[2][t];
        o.w = bias[3] + acc[3][t];
        *(float4*)&g_Xp[(size_t)(t0 + t) * G4 + idx0] = o;
    }
}

// ---------------------------------------------------------------------------
// K4 (R9/R14, best measured): sequential LSTM. 64 blocks x 256 threads.
//   Warp w of block bid owns cell = bid*8 + w.
//   Lane l: gate = l&3 (i,f,g,o), cc = l>>2 (cols [cc*64, cc*64+64)).
//   Poll: per-cell (tag,value), 1 pair per 128B line, pre-sample + re-poll.
// ---------------------------------------------------------------------------
__global__ void __launch_bounds__(256, 1)
k4_lstm(const float* __restrict__ Whh) {
    __shared__ float sh_h[2][8 * 68];   // 68-float stride per 64-chunk

    const int tid  = threadIdx.x;
    const int w    = tid >> 5;
    const int l    = tid & 31;
    const int bid  = blockIdx.x;
    const int gate = l & 3;
    const int cc   = l >> 2;
    const int cell = bid * HC + w;
    const int xidx = (cell << 2) + gate;

    // W_hh chunk: 64 floats = 32 f32x2 pairs
    unsigned long long wp01[16], wp23[16];
    {
        const ulonglong2* wp =
            (const ulonglong2*)(Whh + (size_t)(gate * HH + cell) * HH + cc * 64);
#pragma unroll
        for (int i = 0; i < 16; i++) { ulonglong2 v = wp[i]; wp01[i] = v.x; wp23[i] = v.y; }
    }

    const int pc   = 2 * tid;
    const int spos = (pc >> 6) * 68 + (pc & 63);

    for (int i = tid; i < 8 * 68; i += 256) sh_h[0][i] = 0.0f;
    float xp0 = __ldcg(&g_Xp[(size_t)0 * G4 + xidx]);
    float xp1 = __ldcg(&g_Xp[(size_t)1 * G4 + xidx]);
    __syncthreads();

    float c = 0.0f;
    float* ghs = (float*)g_hs4;
    unsigned long long v0 = 0ull, v1 = 0ull;   // pre-sampled pair

    for (int t = 0; t < TT; t++) {
        // ---- acquire h_{t-1}: pipelined poll (fresh sample issued before check)
        if (t > 0) {
            const unsigned long long* pp = &g_hpk[(t + 1) & 1][tid][0];
            unsigned long long u0, u1;
            asm volatile("ld.relaxed.gpu.global.v2.u64 {%0,%1}, [%2];"
                         : "=l"(u0), "=l"(u1) : "l"(pp) : "memory");
            const unsigned tt = (unsigned)t;
            if ((unsigned)(v0 >> 32) < tt || (unsigned)(v1 >> 32) < tt) {
                v0 = u0; v1 = u1;
                while ((unsigned)(v0 >> 32) < tt || (unsigned)(v1 >> 32) < tt) {
                    asm volatile("ld.relaxed.gpu.global.v2.u64 {%0,%1}, [%2];"
                                 : "=l"(v0), "=l"(v1) : "l"(pp) : "memory");
                }
            }
            *(float2*)&sh_h[t & 1][spos] =
                make_float2(__uint_as_float((unsigned)v0),
                            __uint_as_float((unsigned)v1));
        }
        __syncthreads();

        // ---- W_hh . h partial via packed f32x2 FMA ----
        unsigned long long a01 = 0ull, a23 = 0ull;
        {
            const ulonglong2* hb = (const ulonglong2*)&sh_h[t & 1][cc * 68];
#pragma unroll
            for (int i = 0; i < 16; i++) {
                ulonglong2 hv = hb[i];
                asm("fma.rn.f32x2 %0, %1, %2, %0;"
                    : "+l"(a01) : "l"(wp01[i]), "l"(hv.x));
                asm("fma.rn.f32x2 %0, %1, %2, %0;"
                    : "+l"(a23) : "l"(wp23[i]), "l"(hv.y));
            }
        }
        float s;
        {
            unsigned lo0, hi0, lo1, hi1;
            asm("mov.b64 {%0,%1}, %2;" : "=r"(lo0), "=r"(hi0) : "l"(a01));
            asm("mov.b64 {%0,%1}, %2;" : "=r"(lo1), "=r"(hi1) : "l"(a23));
            s = (__uint_as_float(lo0) + __uint_as_float(hi0))
              + (__uint_as_float(lo1) + __uint_as_float(hi1));
        }
        s += __shfl_xor_sync(0xffffffffu, s, 4);
        s += __shfl_xor_sync(0xffffffffu, s, 8);
        s += __shfl_xor_sync(0xffffffffu, s, 16);
        s += xp0;   // M.x_t + biases, precomputed

        // branchless activation: tanh(x) = 2*sigmoid(2x)-1
        const bool tg = (gate == 2);
        float arg = tg ? 2.0f * s : s;
        float sg  = __fdividef(1.0f, 1.0f + __expf(-arg));
        float act = tg ? 2.0f * sg - 1.0f : sg;

        float iv = __shfl_sync(0xffffffffu, act, 0, 4);
        float fv = __shfl_sync(0xffffffffu, act, 1, 4);
        float gv = __shfl_sync(0xffffffffu, act, 2, 4);
        float ov = __shfl_sync(0xffffffffu, act, 3, 4);

        c = fv * c + iv * gv;
        float th = 2.0f * __fdividef(1.0f, 1.0f + __expf(-2.0f * c)) - 1.0f;
        float hv = ov * th;

        // ---- publish immediately (per-warp) ----
        if (l == 0) {
            unsigned long long pk =
                ((unsigned long long)(unsigned)(t + 1) << 32) |
                (unsigned long long)__float_as_uint(hv);
            asm volatile("st.relaxed.gpu.global.u64 [%0], %1;"
                         :: "l"(&g_hpk[t & 1][cell >> 1][cell & 1]), "l"(pk)
                         : "memory");
            ghs[(size_t)t * HH + cell] = hv;
        }

        // roll Xp prefetch (2 ahead, off critical path)
        xp0 = xp1;
        xp1 = (t + 2 < TT) ? __ldcg(&g_Xp[(size_t)(t + 2) * G4 + xidx]) : 0.0f;

        // pre-sample next step's pair
        {
            const unsigned long long* pn = &g_hpk[t & 1][tid][0];
            asm volatile("ld.relaxed.gpu.global.v2.u64 {%0,%1}, [%2];"
                         : "=l"(v0), "=l"(v1) : "l"(pn) : "memory");
        }
    }
}

// ---------------------------------------------------------------------------
// K5 v2: 16-timestep tiles (512 blocks) — halves fc1w L2 traffic, amortizes
// the wr[16] register tile over 16 t. shz aliases shh (dead after fc1).
// ---------------------------------------------------------------------------
#define REC_OFF 0
#define MU_OFF  (TT * NN * FIN)                 // 573440
#define LV_OFF  (MU_OFF + TT * LAT)             // 1622016

__global__ void __launch_bounds__(256)
k5_post(const float* __restrict__ eps,
        const float* __restrict__ fc1w, const float* __restrict__ fc1b,
        const float* __restrict__ fc2w, const float* __restrict__ fc2b,
        float* __restrict__ out) {
    __shared__ float shh[T5 * HH];      // 32 KB
    __shared__ float shfc[T5][256];     // 16 KB  (total = 48 KB static)
    float (*shz)[LAT] = (float(*)[LAT])shh;   // alias: shh dead after fc1

    int tid  = threadIdx.x;
    int w    = tid >> 5;
    int lane = tid & 31;
    int t0   = blockIdx.x * T5;

    for (int i = tid; i < T5 * HH / 4; i += 256)
        ((float4*)shh)[i] = ((const float4*)g_hs4)[(size_t)t0 * (HH / 4) + i];
    __syncthreads();

    // fc1: 256 outputs, warp w does rows [w*32, w*32+32), all 16 t per row
    for (int i = 0; i < 32; i++) {
        int j = w * 32 + i;
        float wr[16];
#pragma unroll
        for (int u = 0; u < 16; u++)
            wr[u] = __ldg(fc1w + (size_t)j * HH + u * 32 + lane);
#pragma unroll
        for (int ttk = 0; ttk < T5; ttk++) {
            float p = 0.0f;
#pragma unroll
            for (int u = 0; u < 16; u++)
                p += wr[u] * shh[ttk * HH + u * 32 + lane];
            p += __shfl_xor_sync(0xffffffffu, p, 16);
            p += __shfl_xor_sync(0xffffffffu, p, 8);
            p += __shfl_xor_sync(0xffffffffu, p, 4);
            p += __shfl_xor_sync(0xffffffffu, p, 2);
            p += __shfl_xor_sync(0xffffffffu, p, 1);
            if (lane == 0) shfc[ttk][j] = fmaxf(p + fc1b[j], 0.0f);
        }
    }
    __syncthreads();

    // VAE reparam + mu / log_var outputs (shz overwrites shh region)
    for (int i = tid; i < T5 * LAT; i += 256) {
        int ttk = i >> 7, j = i & 127;
        int t = t0 + ttk;
        float mu = shfc[ttk][j];
        float lv = shfc[ttk][LAT + j];
        out[MU_OFF + (size_t)t * LAT + j] = mu;
        out[LV_OFF + (size_t)t * LAT + j] = lv;
        shz[ttk][j] = mu + eps[(size_t)t * LAT + j] * expf(0.5f * lv);
    }
    __syncthreads();

    // fc2 + sigmoid -> rec
    for (int i = 0; i < 9; i++) {
        int j = w + 8 * i;
        if (j < NF) {
            float wr[4];
#pragma unroll
            for (int u = 0; u < 4; u++)
                wr[u] = __ldg(fc2w + (size_t)j * LAT + u * 32 + lane);
#pragma unroll
            for (int ttk = 0; ttk < T5; ttk++) {
                float p = 0.0f;
#pragma unroll
                for (int u = 0; u < 4; u++)
                    p += wr[u] * shz[ttk][u * 32 + lane];
                p += __shfl_xor_sync(0xffffffffu, p, 16);
                p += __shfl_xor_sync(0xffffffffu, p, 8);
                p += __shfl_xor_sync(0xffffffffu, p, 4);
                p += __shfl_xor_sync(0xffffffffu, p, 2);
                p += __shfl_xor_sync(0xffffffffu, p, 1);
                if (lane == 0)
                    out[REC_OFF + (size_t)(t0 + ttk) * NF + j] =
                        1.0f / (1.0f + expf(-(p + fc2b[j])));
            }
        }
    }
}

// ---------------------------------------------------------------------------
extern "C" void kernel_launch(void* const* d_in, const int* in_sizes, int n_in,
                              void* d_out, int out_size) {
    const float* x     = (const float*)d_in[0];
    const float* eps   = (const float*)d_in[1];
    const float* Wrel  = (const float*)d_in[2];
    const float* Wroot = (const float*)d_in[3];
    const float* brg   = (const float*)d_in[4];
    const float* Wih   = (const float*)d_in[5];
    const float* Whh   = (const float*)d_in[6];
    const float* bih   = (const float*)d_in[7];
    const float* bhh   = (const float*)d_in[8];
    const float* fc1w  = (const float*)d_in[9];
    const float* fc1b  = (const float*)d_in[10];
    const float* fc2w  = (const float*)d_in[11];
    const float* fc2b  = (const float*)d_in[12];
    const int*   eidx  = (const int*)d_in[13];
    const int*   etyp  = (const int*)d_in[14];
    float* out = (float*)d_out;

    k1_build_G<<<1, 256>>>(Wrel, Wroot, eidx, etyp);
    k2_build_M<<<32, 256>>>(Wih, bih, bhh, brg);
    k3_reset<<<1, 256>>>();
    k6_xpre<<<2 * (TT / T6), 256>>>(x);
    k4_lstm<<<NBLK, 256>>>(Whh);
    k5_post<<<TT / T5, 256>>>(eps, fc1w, fc1b, fc2w, fc2b, out);
}

// round 17
// speedup vs baseline: 1.3705x; 1.0141x over previous
#include <cuda_runtime.h>
#include <cuda_bf16.h>

// Problem constants
#define TT    8192
#define NN    10
#define FIN   7
#define NF    70      // N*F_IN
#define NFP   72      // padded
#define OO    64
#define HH    512
#define G4    2048    // 4*H
#define LAT   128
#define EE    40
#define RR    2
#define NBLK  64      // recurrent blocks
#define HC    8       // H cells per block (512/64)
#define T6    16      // timesteps per block in k6

// Scratch (device globals; no dynamic allocation allowed)
__device__ float              g_G[NN * NN * FIN * OO];   // [n][m][f][o]
__device__ float              g_M[G4 * NFP];             // [2048][72]
__device__ float              g_biasx[G4];
__device__ float              g_Xp[(size_t)TT * G4];     // [t][cell*4+gate]
// (tag<<32)|h_bits, double-buffered; ONE pair (2 cells) per 128B line.
__device__ unsigned long long g_hpk[2][HH / 2][16];
__device__ float4             g_hs4[TT * HH / 4];        // all h_t (16.8 MB)

// ---------------------------------------------------------------------------
// K1: build G[n][m][f][o] from edges
// ---------------------------------------------------------------------------
__global__ void k1_build_G(const float* __restrict__ Wrel,
                           const float* __restrict__ Wroot,
                           const int*   __restrict__ eidx,
                           const int*   __restrict__ etyp) {
    __shared__ int   cc[RR][NN][NN];
    __shared__ float inv[RR][NN];
    int tid = threadIdx.x;
    for (int i = tid; i < RR * NN * NN; i += 256) ((int*)cc)[i] = 0;
    __syncthreads();
    if (tid < EE) {
        int s = eidx[tid];
        int d = eidx[EE + tid];
        int r = etyp[tid];
        atomicAdd(&cc[r][d][s], 1);
    }
    __syncthreads();
    if (tid < RR * NN) {
        int r = tid / NN, n = tid % NN;
        int cnt = 0;
        for (int m = 0; m < NN; m++) cnt += cc[r][n][m];
        inv[r][n] = 1.0f / fmaxf((float)cnt, 1.0f);
    }
    __syncthreads();
    for (int idx = tid; idx < NN * NN * FIN * OO; idx += 256) {
        int o = idx & 63;
        int f = (idx >> 6) % FIN;
        int m = (idx / (FIN * OO)) % NN;
        int n = idx / (NN * FIN * OO);
        float v = inv[0][n] * (float)cc[0][n][m] * Wrel[(0 * FIN + f) * OO + o]
                + inv[1][n] * (float)cc[1][n][m] * Wrel[(1 * FIN + f) * OO + o];
        if (n == m) v += Wroot[f * OO + o];
        g_G[idx] = v;
    }
}

// ---------------------------------------------------------------------------
// K2: M = W_ih * A  (2048x72), biasx = b_ih + b_hh + W_ih*b_rgcn
// ---------------------------------------------------------------------------
__global__ void k2_build_M(const float* __restrict__ Wih,
                           const float* __restrict__ bih,
                           const float* __restrict__ bhh,
                           const float* __restrict__ brg) {
    __shared__ float Aw[64][65];
    __shared__ float Bg[80][65];
    int g0  = blockIdx.x * 64;
    int tid = threadIdx.x;
    int ty  = tid >> 4, tx = tid & 15;
    float acc[4][5];
#pragma unroll
    for (int u = 0; u < 4; u++)
#pragma unroll
        for (int v = 0; v < 5; v++) acc[u][v] = 0.0f;

    for (int n = 0; n < NN; n++) {
        __syncthreads();
        for (int i = tid; i < 64 * 64; i += 256) {
            int r = i >> 6, c = i & 63;
            Aw[r][c] = Wih[(g0 + r) * (NN * OO) + n * OO + c];
        }
        for (int i = tid; i < 80 * 64; i += 256) {
            int j = i >> 6, o = i & 63;
            Bg[j][o] = (j < NF)
                ? g_G[((n * NN + (j / FIN)) * FIN + (j % FIN)) * OO + o]
                : 0.0f;
        }
        __syncthreads();
        for (int o = 0; o < 64; o++) {
            float a[4], b[5];
#pragma unroll
            for (int u = 0; u < 4; u++) a[u] = Aw[ty * 4 + u][o];
#pragma unroll
            for (int v = 0; v < 5; v++) b[v] = Bg[tx * 5 + v][o];
#pragma unroll
            for (int u = 0; u < 4; u++)
#pragma unroll
                for (int v = 0; v < 5; v++) acc[u][v] += a[u] * b[v];
        }
    }
#pragma unroll
    for (int u = 0; u < 4; u++)
#pragma unroll
        for (int v = 0; v < 5; v++) {
            int j = tx * 5 + v;
            if (j < NFP)
                g_M[(g0 + ty * 4 + u) * NFP + j] = acc[u][v];
        }

    __syncthreads();
    if (tid < 64) {
        int g = g0 + tid;
        float s = bih[g] + bhh[g];
        for (int q = 0; q < NN * OO; q++) s += Wih[g * (NN * OO) + q] * brg[q & 63];
        g_biasx[g] = s;
    }
}

// ---------------------------------------------------------------------------
// K3: reset tagged h words (must run before K4 on every graph replay)
// ---------------------------------------------------------------------------
__global__ void k3_reset() {
    int tid = threadIdx.x;
    for (int i = tid; i < 2 * (HH / 2) * 16; i += 256)
        ((unsigned long long*)g_hpk)[i] = 0ull;   // tag 0, value 0.0f
}

// ---------------------------------------------------------------------------
// K6 (R14, measured 79us): register-tiled GEMM Xp = biasx + M.x
// ---------------------------------------------------------------------------
__global__ void __launch_bounds__(256)
k6_xpre(const float* __restrict__ x) {
    __shared__ float shx_t[NFP][T6];   // [72][16] transposed
    int tid  = threadIdx.x;
    int tc   = blockIdx.x >> 1;
    int half = blockIdx.x & 1;
    int t0   = tc * T6;

    for (int i = tid; i < T6 * NF; i += 256) {
        int tt = i / NF, j = i % NF;
        shx_t[j][tt] = x[(size_t)(t0 + tt) * NF + j];
    }
    if (tid < 2 * T6) shx_t[70 + (tid >> 4)][tid & 15] = 0.0f;
    __syncthreads();

    const int idx0 = half * 1024 + tid * 4;
    const int cell = idx0 >> 2;

    float bias[4];
#pragma unroll
    for (int g = 0; g < 4; g++) bias[g] = g_biasx[g * HH + cell];

    float acc[4][T6];
#pragma unroll
    for (int g = 0; g < 4; g++)
#pragma unroll
        for (int t = 0; t < T6; t++) acc[g][t] = 0.0f;

#pragma unroll
    for (int jc = 0; jc < NFP / 8; jc++) {
        float ms[4][8];
#pragma unroll
        for (int g = 0; g < 4; g++) {
            const float4* mp =
                (const float4*)&g_M[(g * HH + cell) * NFP + jc * 8];
            float4 a = mp[0], b = mp[1];
            ms[g][0] = a.x; ms[g][1] = a.y; ms[g][2] = a.z; ms[g][3] = a.w;
            ms[g][4] = b.x; ms[g][5] = b.y; ms[g][6] = b.z; ms[g][7] = b.w;
        }
#pragma unroll
        for (int jj = 0; jj < 8; jj++) {
            int j = jc * 8 + jj;
#pragma unroll
            for (int tg = 0; tg < 4; tg++) {
                float4 xv = *(const float4*)&shx_t[j][tg * 4];
#pragma unroll
                for (int g = 0; g < 4; g++) {
                    acc[g][tg * 4 + 0] += ms[g][jj] * xv.x;
                    acc[g][tg * 4 + 1] += ms[g][jj] * xv.y;
                    acc[g][tg * 4 + 2] += ms[g][jj] * xv.z;
                    acc[g][tg * 4 + 3] += ms[g][jj] * xv.w;
                }
            }
        }
    }

#pragma unroll
    for (int t = 0; t < T6; t++) {
        float4 o;
        o.x = bias[0] + acc[0][t];
        o.y = bias[1] + acc[1][t];
        o.z = bias[2] + acc[2][t];
        o.w = bias[3] + acc[3][t];
        *(float4*)&g_Xp[(size_t)(t0 + t) * G4 + idx0] = o;
    }
}

// ---------------------------------------------------------------------------
// K4 (R9/R14, best measured): sequential LSTM. 64 blocks x 256 threads.
//   Warp w of block bid owns cell = bid*8 + w.
//   Lane l: gate = l&3 (i,f,g,o), cc = l>>2 (cols [cc*64, cc*64+64)).
//   Poll: per-cell (tag,value), 1 pair per 128B line, pre-sample + re-poll.
// ---------------------------------------------------------------------------
__global__ void __launch_bounds__(256, 1)
k4_lstm(const float* __restrict__ Whh) {
    __shared__ float sh_h[2][8 * 68];   // 68-float stride per 64-chunk

    const int tid  = threadIdx.x;
    const int w    = tid >> 5;
    const int l    = tid & 31;
    const int bid  = blockIdx.x;
    const int gate = l & 3;
    const int cc   = l >> 2;
    const int cell = bid * HC + w;
    const int xidx = (cell << 2) + gate;

    // W_hh chunk: 64 floats = 32 f32x2 pairs
    unsigned long long wp01[16], wp23[16];
    {
        const ulonglong2* wp =
            (const ulonglong2*)(Whh + (size_t)(gate * HH + cell) * HH + cc * 64);
#pragma unroll
        for (int i = 0; i < 16; i++) { ulonglong2 v = wp[i]; wp01[i] = v.x; wp23[i] = v.y; }
    }

    const int pc   = 2 * tid;
    const int spos = (pc >> 6) * 68 + (pc & 63);

    for (int i = tid; i < 8 * 68; i += 256) sh_h[0][i] = 0.0f;
    float xp0 = __ldcg(&g_Xp[(size_t)0 * G4 + xidx]);
    float xp1 = __ldcg(&g_Xp[(size_t)1 * G4 + xidx]);
    __syncthreads();

    float c = 0.0f;
    float* ghs = (float*)g_hs4;
    unsigned long long v0 = 0ull, v1 = 0ull;   // pre-sampled pair

    for (int t = 0; t < TT; t++) {
        // ---- acquire h_{t-1}: pipelined poll (fresh sample issued before check)
        if (t > 0) {
            const unsigned long long* pp = &g_hpk[(t + 1) & 1][tid][0];
            unsigned long long u0, u1;
            asm volatile("ld.relaxed.gpu.global.v2.u64 {%0,%1}, [%2];"
                         : "=l"(u0), "=l"(u1) : "l"(pp) : "memory");
            const unsigned tt = (unsigned)t;
            if ((unsigned)(v0 >> 32) < tt || (unsigned)(v1 >> 32) < tt) {
                v0 = u0; v1 = u1;
                while ((unsigned)(v0 >> 32) < tt || (unsigned)(v1 >> 32) < tt) {
                    asm volatile("ld.relaxed.gpu.global.v2.u64 {%0,%1}, [%2];"
                                 : "=l"(v0), "=l"(v1) : "l"(pp) : "memory");
                }
            }
            *(float2*)&sh_h[t & 1][spos] =
                make_float2(__uint_as_float((unsigned)v0),
                            __uint_as_float((unsigned)v1));
        }
        __syncthreads();

        // ---- W_hh . h partial via packed f32x2 FMA ----
        unsigned long long a01 = 0ull, a23 = 0ull;
        {
            const ulonglong2* hb = (const ulonglong2*)&sh_h[t & 1][cc * 68];
#pragma unroll
            for (int i = 0; i < 16; i++) {
                ulonglong2 hv = hb[i];
                asm("fma.rn.f32x2 %0, %1, %2, %0;"
                    : "+l"(a01) : "l"(wp01[i]), "l"(hv.x));
                asm("fma.rn.f32x2 %0, %1, %2, %0;"
                    : "+l"(a23) : "l"(wp23[i]), "l"(hv.y));
            }
        }
        float s;
        {
            unsigned lo0, hi0, lo1, hi1;
            asm("mov.b64 {%0,%1}, %2;" : "=r"(lo0), "=r"(hi0) : "l"(a01));
            asm("mov.b64 {%0,%1}, %2;" : "=r"(lo1), "=r"(hi1) : "l"(a23));
            s = (__uint_as_float(lo0) + __uint_as_float(hi0))
              + (__uint_as_float(lo1) + __uint_as_float(hi1));
        }
        s += __shfl_xor_sync(0xffffffffu, s, 4);
        s += __shfl_xor_sync(0xffffffffu, s, 8);
        s += __shfl_xor_sync(0xffffffffu, s, 16);
        s += xp0;   // M.x_t + biases, precomputed

        // branchless activation: tanh(x) = 2*sigmoid(2x)-1
        const bool tg = (gate == 2);
        float arg = tg ? 2.0f * s : s;
        float sg  = __fdividef(1.0f, 1.0f + __expf(-arg));
        float act = tg ? 2.0f * sg - 1.0f : sg;

        float iv = __shfl_sync(0xffffffffu, act, 0, 4);
        float fv = __shfl_sync(0xffffffffu, act, 1, 4);
        float gv = __shfl_sync(0xffffffffu, act, 2, 4);
        float ov = __shfl_sync(0xffffffffu, act, 3, 4);

        c = fv * c + iv * gv;
        float th = 2.0f * __fdividef(1.0f, 1.0f + __expf(-2.0f * c)) - 1.0f;
        float hv = ov * th;

        // ---- publish immediately (per-warp) ----
        if (l == 0) {
            unsigned long long pk =
                ((unsigned long long)(unsigned)(t + 1) << 32) |
                (unsigned long long)__float_as_uint(hv);
            asm volatile("st.relaxed.gpu.global.u64 [%0], %1;"
                         :: "l"(&g_hpk[t & 1][cell >> 1][cell & 1]), "l"(pk)
                         : "memory");
            ghs[(size_t)t * HH + cell] = hv;
        }

        // roll Xp prefetch (2 ahead, off critical path)
        xp0 = xp1;
        xp1 = (t + 2 < TT) ? __ldcg(&g_Xp[(size_t)(t + 2) * G4 + xidx]) : 0.0f;

        // pre-sample next step's pair
        {
            const unsigned long long* pn = &g_hpk[t & 1][tid][0];
            asm volatile("ld.relaxed.gpu.global.v2.u64 {%0,%1}, [%2];"
                         : "=l"(v0), "=l"(v1) : "l"(pn) : "memory");
        }
    }
}

// ---------------------------------------------------------------------------
// K5 (R14, 8-timestep tiles): post-processing
// ---------------------------------------------------------------------------
#define REC_OFF 0
#define MU_OFF  (TT * NN * FIN)                 // 573440
#define LV_OFF  (MU_OFF + TT * LAT)             // 1622016

__global__ void __launch_bounds__(256)
k5_post(const float* __restrict__ eps,
        const float* __restrict__ fc1w, const float* __restrict__ fc1b,
        const float* __restrict__ fc2w, const float* __restrict__ fc2b,
        float* __restrict__ out) {
    __shared__ float shh[8 * HH];
    __shared__ float shfc[8][256];
    __shared__ float shz[8][LAT];

    int tid  = threadIdx.x;
    int w    = tid >> 5;
    int lane = tid & 31;
    int t0   = blockIdx.x * 8;

    for (int i = tid; i < 8 * HH / 4; i += 256)
        ((float4*)shh)[i] = ((const float4*)g_hs4)[(size_t)t0 * (HH / 4) + i];
    __syncthreads();

    // fc1: 256 outputs, warp w does rows [w*32, w*32+32)
    for (int i = 0; i < 32; i++) {
        int j = w * 32 + i;
        float wr[16];
#pragma unroll
        for (int u = 0; u < 16; u++)
            wr[u] = __ldg(fc1w + (size_t)j * HH + u * 32 + lane);
#pragma unroll
        for (int ttk = 0; ttk < 8; ttk++) {
            float p = 0.0f;
#pragma unroll
            for (int u = 0; u < 16; u++)
                p += wr[u] * shh[ttk * HH + u * 32 + lane];
            p += __shfl_xor_sync(0xffffffffu, p, 16);
            p += __shfl_xor_sync(0xffffffffu, p, 8);
            p += __shfl_xor_sync(0xffffffffu, p, 4);
            p += __shfl_xor_sync(0xffffffffu, p, 2);
            p += __shfl_xor_sync(0xffffffffu, p, 1);
            if (lane == 0) shfc[ttk][j] = fmaxf(p + fc1b[j], 0.0f);
        }
    }
    __syncthreads();

    // VAE reparam + mu / log_var outputs
    for (int i = tid; i < 8 * LAT; i += 256) {
        int ttk = i >> 7, j = i & 127;
        int t = t0 + ttk;
        float mu = shfc[ttk][j];
        float lv = shfc[ttk][LAT + j];
        out[MU_OFF + (size_t)t * LAT + j] = mu;
        out[LV_OFF + (size_t)t * LAT + j] = lv;
        shz[ttk][j] = mu + eps[(size_t)t * LAT + j] * expf(0.5f * lv);
    }
    __syncthreads();

    // fc2 + sigmoid -> rec
    for (int i = 0; i < 9; i++) {
        int j = w + 8 * i;
        if (j < NF) {
            float wr[4];
#pragma unroll
            for (int u = 0; u < 4; u++)
                wr[u] = __ldg(fc2w + (size_t)j * LAT + u * 32 + lane);
#pragma unroll
            for (int ttk = 0; ttk < 8; ttk++) {
                float p = 0.0f;
#pragma unroll
                for (int u = 0; u < 4; u++)
                    p += wr[u] * shz[ttk][u * 32 + lane];
                p += __shfl_xor_sync(0xffffffffu, p, 16);
                p += __shfl_xor_sync(0xffffffffu, p, 8);
                p += __shfl_xor_sync(0xffffffffu, p, 4);
                p += __shfl_xor_sync(0xffffffffu, p, 2);
                p += __shfl_xor_sync(0xffffffffu, p, 1);
                if (lane == 0)
                    out[REC_OFF + (size_t)(t0 + ttk) * NF + j] =
                        1.0f / (1.0f + expf(-(p + fc2b[j])));
            }
        }
    }
}

// ---------------------------------------------------------------------------
extern "C" void kernel_launch(void* const* d_in, const int* in_sizes, int n_in,
                              void* d_out, int out_size) {
    const float* x     = (const float*)d_in[0];
    const float* eps   = (const float*)d_in[1];
    const float* Wrel  = (const float*)d_in[2];
    const float* Wroot = (const float*)d_in[3];
    const float* brg   = (const float*)d_in[4];
    const float* Wih   = (const float*)d_in[5];
    const float* Whh   = (const float*)d_in[6];
    const float* bih   = (const float*)d_in[7];
    const float* bhh   = (const float*)d_in[8];
    const float* fc1w  = (const float*)d_in[9];
    const float* fc1b  = (const float*)d_in[10];
    const float* fc2w  = (const float*)d_in[11];
    const float* fc2b  = (const float*)d_in[12];
    const int*   eidx  = (const int*)d_in[13];
    const int*   etyp  = (const int*)d_in[14];
    float* out = (float*)d_out;

    k1_build_G<<<1, 256>>>(Wrel, Wroot, eidx, etyp);
    k2_build_M<<<32, 256>>>(Wih, bih, bhh, brg);
    k3_reset<<<1, 256>>>();
    k6_xpre<<<2 * (TT / T6), 256>>>(x);
    k4_lstm<<<NBLK, 256>>>(Whh);
    k5_post<<<TT / 8, 256>>>(eps, fc1w, fc1b, fc2w, fc2b, out);
}